// round 11
// baseline (speedup 1.0000x reference)
#include <cuda_runtime.h>
#include <cuda_bf16.h>
#include <cstdint>

// ===========================================================================
// GATv2, 3 layers. N=20000, E=320000.
// CSR gather aggregation + split-bf16 mma.sync GEMMs
// (128x128 CTA tiles, 8 warps x 32x64, cp.async dbl-buffer, ldmatrix frags).
// ===========================================================================

#define N_MAX   20000
#define NPAD    20096            // 157 * 128
#define E_MAX   320000
#define SLOPE   0.2f

__device__ __align__(16) float g_FS[N_MAX * 256];
__device__ __align__(16) float g_FD[N_MAX * 256];
__device__ __align__(16) float g_HA[N_MAX * 256];
__device__ __align__(16) __nv_bfloat16 g_AH[NPAD * 256];
__device__ __align__(16) __nv_bfloat16 g_AL[NPAD * 256];
// packed transposed hi/lo weights, zero-padded to 128-row multiples of B tiles
#define WT_TOTAL 360448
__device__ __align__(16) __nv_bfloat16 g_WH[WT_TOTAL];
__device__ __align__(16) __nv_bfloat16 g_WL[WT_TOTAL];
__device__ __align__(16) float g_BR2M[64];
__device__ int g_CNT[N_MAX];
__device__ int g_ROWPTR[N_MAX + 1];
__device__ int g_CURS[N_MAX];
__device__ int g_COL[E_MAX];

static inline int cdiv(int a, int b) { return (a + b - 1) / b; }

// ===========================================================================
// CSR build
// ===========================================================================
__global__ void hist_kernel(const int* __restrict__ dst, int* __restrict__ cnt, int E) {
    int e = blockIdx.x * blockDim.x + threadIdx.x;
    if (e < E) atomicAdd(&cnt[dst[e]], 1);
}

__global__ __launch_bounds__(1024) void scan_kernel(
    const int* __restrict__ cnt, int* __restrict__ rowptr, int* __restrict__ curs, int n)
{
    __shared__ int part[1024];
    const int t = threadIdx.x;
    const int CH = (n + 1023) / 1024;
    const int base = t * CH;
    int s = 0;
    for (int i = 0; i < CH; i++) {
        int idx = base + i;
        if (idx < n) s += cnt[idx];
    }
    part[t] = s;
    __syncthreads();
    for (int off = 1; off < 1024; off <<= 1) {
        int v = (t >= off) ? part[t - off] : 0;
        __syncthreads();
        part[t] += v;
        __syncthreads();
    }
    int run = (t > 0) ? part[t - 1] : 0;
    for (int i = 0; i < CH; i++) {
        int idx = base + i;
        if (idx < n) { rowptr[idx] = run; curs[idx] = run; run += cnt[idx]; }
    }
    if (t == 1023) rowptr[n] = part[1023];
}

__global__ void fill_kernel(const int* __restrict__ src, const int* __restrict__ dst,
                            int* __restrict__ curs, int* __restrict__ col, int E) {
    int e = blockIdx.x * blockDim.x + threadIdx.x;
    if (e < E) {
        int pos = atomicAdd(&curs[dst[e]], 1);
        col[pos] = src[e];
    }
}

// ===========================================================================
// Weight conversion: transpose + bf16 hi/lo split, zero-padded.
// Packed layout (elements):
//  j0 W0s  K128 Mpad256 off 0       j1 W0d  off 32768
//  j2 W1s  K256 Mpad256 off 65536   j3 W1d  off 131072
//  j4 W2s  K256 Mpad256 off 196608  j5 W2d  off 262144  (real M 192)
//  j6 Wr2m K256 Mpad128 off 327680  (head-mean, cols<32 valid)
// ===========================================================================
struct WcP { const float* W[6]; const float* Wr2; const float* br2; };

__global__ void wconv_kernel(WcP P, __nv_bfloat16* __restrict__ WH,
                             __nv_bfloat16* __restrict__ WL, float* __restrict__ bm) {
    int i = blockIdx.x * blockDim.x + threadIdx.x;
    if (i < 64) {
        float v = 0.f;
        if (i < 32) {
            #pragma unroll
            for (int h = 0; h < 6; h++) v += P.br2[h * 32 + i];
            v *= (1.f / 6.f);
        }
        bm[i] = v;
    }
    if (i >= WT_TOTAL) return;
    const int offs[8]  = {0, 32768, 65536, 131072, 196608, 262144, 327680, 360448};
    const int Ks[7]    = {128, 128, 256, 256, 256, 256, 256};
    const int realM[7] = {256, 256, 256, 256, 192, 192, 32};
    const int srcLD[7] = {256, 256, 256, 256, 192, 192, 192};
    int j = 0;
    #pragma unroll
    for (int q = 1; q < 7; q++) if (i >= offs[q]) j = q;
    int local = i - offs[j];
    int K = Ks[j];
    int n = local / K, k = local % K;
    float v = 0.f;
    if (j < 6) {
        if (n < realM[j]) v = P.W[j][(size_t)k * srcLD[j] + n];
    } else {
        if (n < 32) {
            #pragma unroll
            for (int h = 0; h < 6; h++) v += P.Wr2[(size_t)k * 192 + h * 32 + n];
            v *= (1.f / 6.f);
        }
    }
    __nv_bfloat16 h = __float2bfloat16(v);
    WH[i] = h;
    WL[i] = __float2bfloat16(v - __bfloat162float(h));
}

__global__ void conv_x_kernel(const float* __restrict__ x,
                              __nv_bfloat16* __restrict__ AH,
                              __nv_bfloat16* __restrict__ AL, int n) {
    int i = blockIdx.x * blockDim.x + threadIdx.x;
    if (i >= n) return;
    float v = x[i];
    __nv_bfloat16 h = __float2bfloat16(v);
    AH[i] = h;
    AL[i] = __float2bfloat16(v - __bfloat162float(h));
}

// ===========================================================================
// Split-bf16 mma GEMM v5.
// CTA 128x128, 256 thr / 8 warps (4m x 2n), warp tile 32x64, K staged 32.
// cp.async.cg double-buffered smem; ldmatrix frags; per-entry valid cols.
// D = Ah*Bh + Al*Bh + Ah*Bl (fp32 accum).
// ===========================================================================
#define SPAD 40   // bf16 pitch (80 B, 16B-aligned, conflict-free ldmatrix)

struct MmaP {
    int   selMap[8];
    int   colMap[8];
    int   validMap[8];
    int   woff[3];
    const float* bias[3];
    float* C[3];
    int   Cld[3];
};

__device__ __forceinline__ void mma_bf16(float d[4], const uint32_t a[4],
                                         const uint32_t b[2]) {
    asm volatile(
        "mma.sync.aligned.m16n8k16.row.col.f32.bf16.bf16.f32 "
        "{%0,%1,%2,%3}, {%4,%5,%6,%7}, {%8,%9}, {%0,%1,%2,%3};"
        : "+f"(d[0]), "+f"(d[1]), "+f"(d[2]), "+f"(d[3])
        : "r"(a[0]), "r"(a[1]), "r"(a[2]), "r"(a[3]), "r"(b[0]), "r"(b[1]));
}

__device__ __forceinline__ void ldsm_x4(uint32_t r[4], const __nv_bfloat16* p) {
    uint32_t a = (uint32_t)__cvta_generic_to_shared(p);
    asm volatile("ldmatrix.sync.aligned.m8n8.x4.shared.b16 {%0,%1,%2,%3}, [%4];"
                 : "=r"(r[0]), "=r"(r[1]), "=r"(r[2]), "=r"(r[3]) : "r"(a));
}

__device__ __forceinline__ void cp16(void* smem, const void* g) {
    uint32_t s = (uint32_t)__cvta_generic_to_shared(smem);
    asm volatile("cp.async.cg.shared.global [%0], [%1], 16;" :: "r"(s), "l"(g));
}
#define CP_COMMIT() asm volatile("cp.async.commit_group;" ::: "memory")

__global__ __launch_bounds__(256, 2) void gemm_mma_kernel(
    const __nv_bfloat16* __restrict__ AH, const __nv_bfloat16* __restrict__ AL,
    const __nv_bfloat16* __restrict__ WHg, const __nv_bfloat16* __restrict__ WLg,
    MmaP P, int Nrows, int K)
{
    __shared__ __align__(16) __nv_bfloat16 sA[2][2][128][SPAD];  // [buf][hi/lo]
    __shared__ __align__(16) __nv_bfloat16 sB[2][2][128][SPAD];

    const int tid  = threadIdx.x;
    const int wid  = tid >> 5;
    const int lane = tid & 31;
    const int wm   = wid & 3;      // 0..3 : 32 rows each
    const int wn   = wid >> 2;     // 0..1 : 64 cols each

    const int sel     = P.selMap[blockIdx.y];
    const int colBase = P.colMap[blockIdx.y];
    const int valid   = P.validMap[blockIdx.y];
    const int rowBase = blockIdx.x * 128;

    const __nv_bfloat16* __restrict__ WH = WHg + P.woff[sel];
    const __nv_bfloat16* __restrict__ WL = WLg + P.woff[sel];

    float acc[2][2][4][4];   // [mt][nh][nt][frag]
    #pragma unroll
    for (int a = 0; a < 2; a++)
        #pragma unroll
        for (int b = 0; b < 2; b++)
            #pragma unroll
            for (int c = 0; c < 4; c++)
                #pragma unroll
                for (int d = 0; d < 4; d++) acc[a][b][c][d] = 0.f;

    // ldmatrix source mappings
    const int aRow = (lane & 15);
    const int aColOff = ((lane >> 4) << 3);
    const int bRow = (lane & 7) | ((lane & 16) >> 1);
    const int bColOff = (lane & 8);

    const int nStages = K / 32;

    // stage fill: A 128 rows + B 128 rows, hi+lo, 32 k-cols; 256 threads.
    auto fill = [&](int s, int buf) {
        const int kB = s * 32;
        #pragma unroll
        for (int i = 0; i < 2; i++) {
            int j = tid * 2 + i;
            int r = j >> 2, sl = j & 3;
            cp16(&sA[buf][0][r][sl * 8], &AH[(size_t)(rowBase + r) * K + kB + sl * 8]);
            cp16(&sA[buf][1][r][sl * 8], &AL[(size_t)(rowBase + r) * K + kB + sl * 8]);
            cp16(&sB[buf][0][r][sl * 8], &WH[(size_t)(colBase + r) * K + kB + sl * 8]);
            cp16(&sB[buf][1][r][sl * 8], &WL[(size_t)(colBase + r) * K + kB + sl * 8]);
        }
        CP_COMMIT();
    };

    fill(0, 0);

    for (int s = 0; s < nStages; s++) {
        const int buf = s & 1;
        if (s + 1 < nStages) {
            fill(s + 1, buf ^ 1);
            asm volatile("cp.async.wait_group 1;" ::: "memory");
        } else {
            asm volatile("cp.async.wait_group 0;" ::: "memory");
        }
        __syncthreads();

        #pragma unroll
        for (int ks = 0; ks < 32; ks += 16) {
            uint32_t ah[2][4], al[2][4];
            #pragma unroll
            for (int mt = 0; mt < 2; mt++) {
                const int r = wm * 32 + mt * 16 + aRow;
                const int c = ks + aColOff;
                ldsm_x4(ah[mt], &sA[buf][0][r][c]);
                ldsm_x4(al[mt], &sA[buf][1][r][c]);
            }
            #pragma unroll
            for (int nh = 0; nh < 2; nh++) {
                uint32_t bh[4][2], bl[4][2];
                #pragma unroll
                for (int np = 0; np < 2; np++) {
                    const int n0 = wn * 64 + nh * 32 + np * 16 + bRow;
                    const int c = ks + bColOff;
                    uint32_t t[4];
                    ldsm_x4(t, &sB[buf][0][n0][c]);
                    bh[np * 2][0] = t[0];     bh[np * 2][1] = t[1];
                    bh[np * 2 + 1][0] = t[2]; bh[np * 2 + 1][1] = t[3];
                    ldsm_x4(t, &sB[buf][1][n0][c]);
                    bl[np * 2][0] = t[0];     bl[np * 2][1] = t[1];
                    bl[np * 2 + 1][0] = t[2]; bl[np * 2 + 1][1] = t[3];
                }
                #pragma unroll
                for (int mt = 0; mt < 2; mt++)
                    #pragma unroll
                    for (int nt = 0; nt < 4; nt++) {
                        mma_bf16(acc[mt][nh][nt], ah[mt], bh[nt]);
                        mma_bf16(acc[mt][nh][nt], al[mt], bh[nt]);
                        mma_bf16(acc[mt][nh][nt], ah[mt], bl[nt]);
                    }
            }
        }
        __syncthreads();
    }

    // ---- epilogue: bias + store (guarded by valid cols) ----
    const int g  = lane >> 2;
    const int t4 = lane & 3;
    float* C = P.C[sel];
    const int Cld = P.Cld[sel];
    const float* bias = P.bias[sel];
    #pragma unroll
    for (int mt = 0; mt < 2; mt++) {
        const int r0 = rowBase + wm * 32 + mt * 16 + g;
        #pragma unroll
        for (int nh = 0; nh < 2; nh++)
            #pragma unroll
            for (int nt = 0; nt < 4; nt++) {
                const int lc = wn * 64 + nh * 32 + nt * 8 + 2 * t4;
                if (lc >= valid) continue;
                const int cc = colBase + lc;
                const float b0 = __ldg(&bias[cc]);
                const float b1 = __ldg(&bias[cc + 1]);
                if (r0 < Nrows) {
                    float2 v = make_float2(acc[mt][nh][nt][0] + b0, acc[mt][nh][nt][1] + b1);
                    *reinterpret_cast<float2*>(&C[(size_t)r0 * Cld + cc]) = v;
                }
                if (r0 + 8 < Nrows) {
                    float2 v = make_float2(acc[mt][nh][nt][2] + b0, acc[mt][nh][nt][3] + b1);
                    *reinterpret_cast<float2*>(&C[(size_t)(r0 + 8) * Cld + cc]) = v;
                }
            }
    }
}

// ===========================================================================
// Aggregation, layers 0/1 (H=4, D=64), unroll 4; bf16 hi/lo epilogue.
// ===========================================================================
template <int RES, int WRITE_F32>
__global__ __launch_bounds__(128) void gat_agg_h4d64_kernel(
    const int* __restrict__ rowptr, const int* __restrict__ col,
    const float* __restrict__ FS, const float* __restrict__ FD,
    const float* __restrict__ attn,
    const float* __restrict__ resid, float* __restrict__ out,
    __nv_bfloat16* __restrict__ AH, __nv_bfloat16* __restrict__ AL)
{
    const int node = blockIdx.x;
    const int w = threadIdx.x >> 5;
    const int lane = threadIdx.x & 31;

    const int off = w * 64 + lane;
    const float fd0 = FD[(size_t)node * 256 + off];
    const float fd1 = FD[(size_t)node * 256 + off + 32];
    const float at0 = __ldg(&attn[w * 64 + lane]);
    const float at1 = __ldg(&attn[w * 64 + lane + 32]);

    float s0 = 0.f, s1 = 0.f, den = 0.f;

    int p = rowptr[node];
    const int pEnd = rowptr[node + 1];

    for (; p + 4 <= pEnd; p += 4) {
        int sn0 = col[p], sn1 = col[p + 1], sn2 = col[p + 2], sn3 = col[p + 3];
        float f00 = FS[(size_t)sn0 * 256 + off], f01 = FS[(size_t)sn0 * 256 + off + 32];
        float f10 = FS[(size_t)sn1 * 256 + off], f11 = FS[(size_t)sn1 * 256 + off + 32];
        float f20 = FS[(size_t)sn2 * 256 + off], f21 = FS[(size_t)sn2 * 256 + off + 32];
        float f30 = FS[(size_t)sn3 * 256 + off], f31 = FS[(size_t)sn3 * 256 + off + 32];

        float v, t0, t1, t2, t3;
        v = f00 + fd0; v = (v > 0.f) ? v : SLOPE * v; t0  = v * at0;
        v = f01 + fd1; v = (v > 0.f) ? v : SLOPE * v; t0 += v * at1;
        v = f10 + fd0; v = (v > 0.f) ? v : SLOPE * v; t1  = v * at0;
        v = f11 + fd1; v = (v > 0.f) ? v : SLOPE * v; t1 += v * at1;
        v = f20 + fd0; v = (v > 0.f) ? v : SLOPE * v; t2  = v * at0;
        v = f21 + fd1; v = (v > 0.f) ? v : SLOPE * v; t2 += v * at1;
        v = f30 + fd0; v = (v > 0.f) ? v : SLOPE * v; t3  = v * at0;
        v = f31 + fd1; v = (v > 0.f) ? v : SLOPE * v; t3 += v * at1;

        #pragma unroll
        for (int o = 16; o > 0; o >>= 1) {
            t0 += __shfl_xor_sync(0xffffffffu, t0, o);
            t1 += __shfl_xor_sync(0xffffffffu, t1, o);
            t2 += __shfl_xor_sync(0xffffffffu, t2, o);
            t3 += __shfl_xor_sync(0xffffffffu, t3, o);
        }
        float e0 = __expf(t0), e1 = __expf(t1), e2 = __expf(t2), e3 = __expf(t3);
        den += (e0 + e1) + (e2 + e3);
        s0 += f00 * e0 + f10 * e1 + f20 * e2 + f30 * e3;
        s1 += f01 * e0 + f11 * e1 + f21 * e2 + f31 * e3;
    }
    for (; p < pEnd; p++) {
        int sn = col[p];
        float f0 = FS[(size_t)sn * 256 + off];
        float f1 = FS[(size_t)sn * 256 + off + 32];
        float v0 = f0 + fd0; v0 = (v0 > 0.f) ? v0 : SLOPE * v0;
        float v1 = f1 + fd1; v1 = (v1 > 0.f) ? v1 : SLOPE * v1;
        float t = v0 * at0 + v1 * at1;
        #pragma unroll
        for (int o = 16; o > 0; o >>= 1) t += __shfl_xor_sync(0xffffffffu, t, o);
        float ex = __expf(t);
        den += ex; s0 += f0 * ex; s1 += f1 * ex;
    }

    const float inv = (den > 0.f) ? (1.f / den) : 0.f;
    float o0 = s0 * inv;
    float o1 = s1 * inv;
    if (RES) {
        o0 += resid[(size_t)node * 256 + off];
        o1 += resid[(size_t)node * 256 + off + 32];
    }
    o0 = (o0 > 0.f) ? o0 : expm1f(o0);
    o1 = (o1 > 0.f) ? o1 : expm1f(o1);
    if (WRITE_F32) {
        out[(size_t)node * 256 + off]      = o0;
        out[(size_t)node * 256 + off + 32] = o1;
    }
    __nv_bfloat16 h0 = __float2bfloat16(o0);
    __nv_bfloat16 h1 = __float2bfloat16(o1);
    AH[(size_t)node * 256 + off]      = h0;
    AH[(size_t)node * 256 + off + 32] = h1;
    AL[(size_t)node * 256 + off]      = __float2bfloat16(o0 - __bfloat162float(h0));
    AL[(size_t)node * 256 + off + 32] = __float2bfloat16(o1 - __bfloat162float(h1));
}

// ===========================================================================
// Aggregation, layer 2 (H=6, D=32) + head mean + head-averaged residual.
// ===========================================================================
__global__ __launch_bounds__(192) void gat_agg_l2_kernel(
    const int* __restrict__ rowptr, const int* __restrict__ col,
    const float* __restrict__ FS, const float* __restrict__ FD,
    const float* __restrict__ attn,
    const float* __restrict__ resm, float* __restrict__ out)
{
    __shared__ float sm[192];
    const int node = blockIdx.x;
    const int w = threadIdx.x / 32;
    const int lane = threadIdx.x & 31;

    const int off = w * 32 + lane;
    const float fd = FD[(size_t)node * 192 + off];
    const float at = __ldg(&attn[off]);

    float s = 0.f, den = 0.f;

    int p = rowptr[node];
    const int pEnd = rowptr[node + 1];

    for (; p + 4 <= pEnd; p += 4) {
        int sn0 = col[p], sn1 = col[p + 1], sn2 = col[p + 2], sn3 = col[p + 3];
        float f0 = FS[(size_t)sn0 * 192 + off];
        float f1 = FS[(size_t)sn1 * 192 + off];
        float f2 = FS[(size_t)sn2 * 192 + off];
        float f3 = FS[(size_t)sn3 * 192 + off];
        float v, t0, t1, t2, t3;
        v = f0 + fd; v = (v > 0.f) ? v : SLOPE * v; t0 = v * at;
        v = f1 + fd; v = (v > 0.f) ? v : SLOPE * v; t1 = v * at;
        v = f2 + fd; v = (v > 0.f) ? v : SLOPE * v; t2 = v * at;
        v = f3 + fd; v = (v > 0.f) ? v : SLOPE * v; t3 = v * at;
        #pragma unroll
        for (int o = 16; o > 0; o >>= 1) {
            t0 += __shfl_xor_sync(0xffffffffu, t0, o);
            t1 += __shfl_xor_sync(0xffffffffu, t1, o);
            t2 += __shfl_xor_sync(0xffffffffu, t2, o);
            t3 += __shfl_xor_sync(0xffffffffu, t3, o);
        }
        float e0 = __expf(t0), e1 = __expf(t1), e2 = __expf(t2), e3 = __expf(t3);
        den += (e0 + e1) + (e2 + e3);
        s += f0 * e0 + f1 * e1 + f2 * e2 + f3 * e3;
    }
    for (; p < pEnd; p++) {
        int sn = col[p];
        float f = FS[(size_t)sn * 192 + off];
        float v = f + fd; v = (v > 0.f) ? v : SLOPE * v;
        float t = v * at;
        #pragma unroll
        for (int o = 16; o > 0; o >>= 1) t += __shfl_xor_sync(0xffffffffu, t, o);
        float ex = __expf(t);
        den += ex; s += f * ex;
    }

    const float inv = (den > 0.f) ? (1.f / den) : 0.f;
    sm[off] = s * inv;
    __syncthreads();

    if (w == 0) {
        float m = 0.f;
        #pragma unroll
        for (int h = 0; h < 6; h++) m += sm[h * 32 + lane];
        out[(size_t)node * 32 + lane] = m * (1.f / 6.f) + resm[(size_t)node * 64 + lane];
    }
}

// ===========================================================================
// Host driver
// ===========================================================================
extern "C" void kernel_launch(void* const* d_in, const int* in_sizes, int n_in,
                              void* d_out, int out_size)
{
    const float* x   = (const float*)d_in[0];
    const int*   src = (const int*)d_in[1];
    const int*   dst = (const int*)d_in[2];
    const float* W0s = (const float*)d_in[3];
    const float* b0s = (const float*)d_in[4];
    const float* W0d = (const float*)d_in[5];
    const float* b0d = (const float*)d_in[6];
    const float* a0  = (const float*)d_in[7];
    const float* W1s = (const float*)d_in[8];
    const float* b1s = (const float*)d_in[9];
    const float* W1d = (const float*)d_in[10];
    const float* b1d = (const float*)d_in[11];
    const float* a1  = (const float*)d_in[12];
    const float* W2s = (const float*)d_in[13];
    const float* b2s = (const float*)d_in[14];
    const float* W2d = (const float*)d_in[15];
    const float* b2d = (const float*)d_in[16];
    const float* a2  = (const float*)d_in[17];
    const float* Wr2 = (const float*)d_in[18];
    const float* br2 = (const float*)d_in[19];

    const int N = in_sizes[0] / 128;
    const int E = in_sizes[1];

    float *FS, *FD, *HA, *BR2M;
    __nv_bfloat16 *AH, *AL, *WH, *WL;
    int *CNT, *ROWPTR, *CURS, *COL;
    cudaGetSymbolAddress((void**)&FS, g_FS);
    cudaGetSymbolAddress((void**)&FD, g_FD);
    cudaGetSymbolAddress((void**)&HA, g_HA);
    cudaGetSymbolAddress((void**)&BR2M, g_BR2M);
    cudaGetSymbolAddress((void**)&AH, g_AH);
    cudaGetSymbolAddress((void**)&AL, g_AL);
    cudaGetSymbolAddress((void**)&WH, g_WH);
    cudaGetSymbolAddress((void**)&WL, g_WL);
    cudaGetSymbolAddress((void**)&CNT, g_CNT);
    cudaGetSymbolAddress((void**)&ROWPTR, g_ROWPTR);
    cudaGetSymbolAddress((void**)&CURS, g_CURS);
    cudaGetSymbolAddress((void**)&COL, g_COL);

    float* out = (float*)d_out;

    const int TB = 256;
    const int mTiles = cdiv(N, 128);

    // gemm0 at launch slot 5 for ncu sampling
    cudaMemsetAsync(CNT, 0, (size_t)N * sizeof(int), 0);
    {
        WcP wp;
        wp.W[0] = W0s; wp.W[1] = W0d; wp.W[2] = W1s; wp.W[3] = W1d;
        wp.W[4] = W2s; wp.W[5] = W2d; wp.Wr2 = Wr2; wp.br2 = br2;
        wconv_kernel<<<cdiv(WT_TOTAL, TB), TB>>>(wp, WH, WL, BR2M);
    }
    conv_x_kernel<<<cdiv(N * 128, TB), TB>>>(x, AH, AL, N * 128);
    hist_kernel<<<cdiv(E, TB), TB>>>(dst, CNT, E);

    // ---------------- Layer 0 GEMM: K=128 -> FS, FD ----------------
    {
        MmaP P;
        const int sm_[4] = {0, 0, 1, 1};
        const int cm_[4] = {0, 128, 0, 128};
        for (int i = 0; i < 8; i++) {
            P.selMap[i] = sm_[i & 3]; P.colMap[i] = cm_[i & 3]; P.validMap[i] = 128;
        }
        P.woff[0] = 0;     P.bias[0] = b0s; P.C[0] = FS; P.Cld[0] = 256;
        P.woff[1] = 32768; P.bias[1] = b0d; P.C[1] = FD; P.Cld[1] = 256;
        P.woff[2] = 0;     P.bias[2] = b0s; P.C[2] = FS; P.Cld[2] = 256;
        dim3 grid(mTiles, 4);
        gemm_mma_kernel<<<grid, 256>>>(AH, AL, WH, WL, P, N, 128);
    }

    scan_kernel<<<1, 1024>>>(CNT, ROWPTR, CURS, N);
    fill_kernel<<<cdiv(E, TB), TB>>>(src, dst, CURS, COL, E);

    gat_agg_h4d64_kernel<0, 1><<<N, 128>>>(ROWPTR, COL, FS, FD, a0, nullptr, HA, AH, AL);

    // ---------------- Layer 1: K=256 -> FS, FD ----------------
    {
        MmaP P;
        const int sm_[4] = {0, 0, 1, 1};
        const int cm_[4] = {0, 128, 0, 128};
        for (int i = 0; i < 8; i++) {
            P.selMap[i] = sm_[i & 3]; P.colMap[i] = cm_[i & 3]; P.validMap[i] = 128;
        }
        P.woff[0] = 65536;  P.bias[0] = b1s; P.C[0] = FS; P.Cld[0] = 256;
        P.woff[1] = 131072; P.bias[1] = b1d; P.C[1] = FD; P.Cld[1] = 256;
        P.woff[2] = 0;      P.bias[2] = b1s; P.C[2] = FS; P.Cld[2] = 256;
        dim3 grid(mTiles, 4);
        gemm_mma_kernel<<<grid, 256>>>(AH, AL, WH, WL, P, N, 256);
    }
    gat_agg_h4d64_kernel<1, 0><<<N, 128>>>(ROWPTR, COL, FS, FD, a1, HA, nullptr, AH, AL);

    // ---------------- Layer 2: K=256 -> FS, FD (192) + resm (64) ------
    {
        MmaP P;
        const int sm_[5] = {0, 0, 1, 1, 2};
        const int cm_[5] = {0, 128, 0, 128, 0};
        const int vm_[5] = {128, 64, 128, 64, 64};
        for (int i = 0; i < 5; i++) {
            P.selMap[i] = sm_[i]; P.colMap[i] = cm_[i]; P.validMap[i] = vm_[i];
        }
        for (int i = 5; i < 8; i++) { P.selMap[i] = 0; P.colMap[i] = 0; P.validMap[i] = 0; }
        P.woff[0] = 196608; P.bias[0] = b2s;  P.C[0] = FS; P.Cld[0] = 192;
        P.woff[1] = 262144; P.bias[1] = b2d;  P.C[1] = FD; P.Cld[1] = 192;
        P.woff[2] = 327680; P.bias[2] = BR2M; P.C[2] = HA; P.Cld[2] = 64;
        dim3 grid(mTiles, 5);
        gemm_mma_kernel<<<grid, 256>>>(AH, AL, WH, WL, P, N, 256);
    }
    gat_agg_l2_kernel<<<N, 192>>>(ROWPTR, COL, FS, FD, a2, HA, out);
}

// round 12
// speedup vs baseline: 1.0640x; 1.0640x over previous
#include <cuda_runtime.h>
#include <cuda_bf16.h>
#include <cstdint>

// ===========================================================================
// GATv2, 3 layers. N=20000, E=320000.
// CSR gather aggregation (8 lanes/edge) + split-bf16 mma.sync GEMMs
// (R10 config: 8 warps x 32x32 tiles, cp.async dbl-buffer, ldmatrix frags).
// ===========================================================================

#define N_MAX   20000
#define NPAD    20096            // 157 * 128
#define E_MAX   320000
#define SLOPE   0.2f

__device__ __align__(16) float g_FS[N_MAX * 256];
__device__ __align__(16) float g_FD[N_MAX * 256];
__device__ __align__(16) float g_HA[N_MAX * 256];
__device__ __align__(16) __nv_bfloat16 g_AH[NPAD * 256];
__device__ __align__(16) __nv_bfloat16 g_AL[NPAD * 256];
#define WT_TOTAL 311296
__device__ __align__(16) __nv_bfloat16 g_WH[WT_TOTAL];
__device__ __align__(16) __nv_bfloat16 g_WL[WT_TOTAL];
__device__ __align__(16) float g_BR2M[64];
__device__ int g_CNT[N_MAX];
__device__ int g_ROWPTR[N_MAX + 1];
__device__ int g_CURS[N_MAX];
__device__ int g_COL[E_MAX];

static inline int cdiv(int a, int b) { return (a + b - 1) / b; }

// ===========================================================================
// CSR build
// ===========================================================================
__global__ void hist_kernel(const int* __restrict__ dst, int* __restrict__ cnt, int E) {
    int e = blockIdx.x * blockDim.x + threadIdx.x;
    if (e < E) atomicAdd(&cnt[dst[e]], 1);
}

// scan also re-zeroes cnt (so no memset launch is needed; globals start zeroed)
__global__ __launch_bounds__(1024) void scan_kernel(
    int* __restrict__ cnt, int* __restrict__ rowptr, int* __restrict__ curs, int n)
{
    __shared__ int part[1024];
    const int t = threadIdx.x;
    const int CH = (n + 1023) / 1024;
    const int base = t * CH;
    int s = 0;
    for (int i = 0; i < CH; i++) {
        int idx = base + i;
        if (idx < n) s += cnt[idx];
    }
    part[t] = s;
    __syncthreads();
    for (int off = 1; off < 1024; off <<= 1) {
        int v = (t >= off) ? part[t - off] : 0;
        __syncthreads();
        part[t] += v;
        __syncthreads();
    }
    int run = (t > 0) ? part[t - 1] : 0;
    for (int i = 0; i < CH; i++) {
        int idx = base + i;
        if (idx < n) {
            int c = cnt[idx];
            cnt[idx] = 0;                 // ready for next replay
            rowptr[idx] = run;
            curs[idx]   = run;
            run += c;
        }
    }
    if (t == 1023) rowptr[n] = part[1023];
}

__global__ void fill_kernel(const int* __restrict__ src, const int* __restrict__ dst,
                            int* __restrict__ curs, int* __restrict__ col, int E) {
    int e = blockIdx.x * blockDim.x + threadIdx.x;
    if (e < E) {
        int pos = atomicAdd(&curs[dst[e]], 1);
        col[pos] = src[e];
    }
}

// ===========================================================================
// Weight conversion: transpose + bf16 hi/lo split (packed; j=6 = head-mean Wr2)
// ===========================================================================
struct WcP { const float* W[6]; const float* Wr2; const float* br2; };

__global__ void wconv_kernel(WcP P, __nv_bfloat16* __restrict__ WH,
                             __nv_bfloat16* __restrict__ WL, float* __restrict__ bm) {
    int i = blockIdx.x * blockDim.x + threadIdx.x;
    if (i < 64) {
        float v = 0.f;
        if (i < 32) {
            #pragma unroll
            for (int h = 0; h < 6; h++) v += P.br2[h * 32 + i];
            v *= (1.f / 6.f);
        }
        bm[i] = v;
    }
    if (i >= WT_TOTAL) return;
    const int offs[8] = {0, 32768, 65536, 131072, 196608, 245760, 294912, 311296};
    const int Ks[7]   = {128, 128, 256, 256, 256, 256, 256};
    const int Ms[7]   = {256, 256, 256, 256, 192, 192, 64};
    int j = 0;
    #pragma unroll
    for (int q = 1; q < 7; q++) if (i >= offs[q]) j = q;
    int local = i - offs[j];
    int K = Ks[j];
    int n = local / K, k = local % K;
    float v;
    if (j < 6) {
        v = P.W[j][(size_t)k * Ms[j] + n];
    } else {
        v = 0.f;
        if (n < 32) {
            #pragma unroll
            for (int h = 0; h < 6; h++) v += P.Wr2[(size_t)k * 192 + h * 32 + n];
            v *= (1.f / 6.f);
        }
    }
    __nv_bfloat16 h = __float2bfloat16(v);
    WH[i] = h;
    WL[i] = __float2bfloat16(v - __bfloat162float(h));
}

__global__ void conv_x_kernel(const float* __restrict__ x,
                              __nv_bfloat16* __restrict__ AH,
                              __nv_bfloat16* __restrict__ AL, int n) {
    int i = blockIdx.x * blockDim.x + threadIdx.x;
    if (i >= n) return;
    float v = x[i];
    __nv_bfloat16 h = __float2bfloat16(v);
    AH[i] = h;
    AL[i] = __float2bfloat16(v - __bfloat162float(h));
}

// ===========================================================================
// Split-bf16 mma GEMM (R10 config).
// CTA 128x64, 256 thr / 8 warps (4m x 2n), warp tile 32x32, K staged 32.
// cp.async.cg double-buffered smem; ldmatrix frag loads.
// D = Ah*Bh + Al*Bh + Ah*Bl (fp32 accum).
// ===========================================================================
#define SPAD 40

struct MmaP {
    int   selMap[8];
    int   colMap[8];
    int   woff[3];
    const float* bias[3];
    float* C[3];
    int   Cld[3];
};

__device__ __forceinline__ void mma_bf16(float d[4], const uint32_t a[4],
                                         const uint32_t b[2]) {
    asm volatile(
        "mma.sync.aligned.m16n8k16.row.col.f32.bf16.bf16.f32 "
        "{%0,%1,%2,%3}, {%4,%5,%6,%7}, {%8,%9}, {%0,%1,%2,%3};"
        : "+f"(d[0]), "+f"(d[1]), "+f"(d[2]), "+f"(d[3])
        : "r"(a[0]), "r"(a[1]), "r"(a[2]), "r"(a[3]), "r"(b[0]), "r"(b[1]));
}

__device__ __forceinline__ void ldsm_x4(uint32_t r[4], const __nv_bfloat16* p) {
    uint32_t a = (uint32_t)__cvta_generic_to_shared(p);
    asm volatile("ldmatrix.sync.aligned.m8n8.x4.shared.b16 {%0,%1,%2,%3}, [%4];"
                 : "=r"(r[0]), "=r"(r[1]), "=r"(r[2]), "=r"(r[3]) : "r"(a));
}

__device__ __forceinline__ void cp16(void* smem, const void* g) {
    uint32_t s = (uint32_t)__cvta_generic_to_shared(smem);
    asm volatile("cp.async.cg.shared.global [%0], [%1], 16;" :: "r"(s), "l"(g));
}
#define CP_COMMIT() asm volatile("cp.async.commit_group;" ::: "memory")

__global__ __launch_bounds__(256) void gemm_mma_kernel(
    const __nv_bfloat16* __restrict__ AH, const __nv_bfloat16* __restrict__ AL,
    const __nv_bfloat16* __restrict__ WHg, const __nv_bfloat16* __restrict__ WLg,
    MmaP P, int Nrows, int K)
{
    __shared__ __align__(16) __nv_bfloat16 sA[2][2][128][SPAD];
    __shared__ __align__(16) __nv_bfloat16 sB[2][2][64][SPAD];

    const int tid  = threadIdx.x;
    const int wid  = tid >> 5;
    const int lane = tid & 31;
    const int wm   = wid & 3;
    const int wn   = wid >> 2;

    const int sel     = P.selMap[blockIdx.y];
    const int colBase = P.colMap[blockIdx.y];
    const int rowBase = blockIdx.x * 128;

    const __nv_bfloat16* __restrict__ WH = WHg + P.woff[sel];
    const __nv_bfloat16* __restrict__ WL = WLg + P.woff[sel];

    float acc[2][4][4];
    #pragma unroll
    for (int i = 0; i < 2; i++)
        #pragma unroll
        for (int j = 0; j < 4; j++)
            #pragma unroll
            for (int q = 0; q < 4; q++) acc[i][j][q] = 0.f;

    const int aRow = (lane & 15);
    const int aColOff = ((lane >> 4) << 3);
    const int bRow = (lane & 7) | ((lane & 16) >> 1);
    const int bColOff = (lane & 8);

    const int nStages = K / 32;

    auto fill = [&](int s, int buf) {
        const int kB = s * 32;
        #pragma unroll
        for (int i = 0; i < 2; i++) {
            int j = tid * 2 + i;
            int r = j >> 2, sl = j & 3;
            cp16(&sA[buf][0][r][sl * 8], &AH[(size_t)(rowBase + r) * K + kB + sl * 8]);
            cp16(&sA[buf][1][r][sl * 8], &AL[(size_t)(rowBase + r) * K + kB + sl * 8]);
        }
        {
            int r = tid >> 2, sl = tid & 3;
            cp16(&sB[buf][0][r][sl * 8], &WH[(size_t)(colBase + r) * K + kB + sl * 8]);
            cp16(&sB[buf][1][r][sl * 8], &WL[(size_t)(colBase + r) * K + kB + sl * 8]);
        }
        CP_COMMIT();
    };

    fill(0, 0);

    for (int s = 0; s < nStages; s++) {
        const int buf = s & 1;
        if (s + 1 < nStages) {
            fill(s + 1, buf ^ 1);
            asm volatile("cp.async.wait_group 1;" ::: "memory");
        } else {
            asm volatile("cp.async.wait_group 0;" ::: "memory");
        }
        __syncthreads();

        #pragma unroll
        for (int ks = 0; ks < 32; ks += 16) {
            uint32_t ah[2][4], al[2][4];
            #pragma unroll
            for (int mt = 0; mt < 2; mt++) {
                const int r = wm * 32 + mt * 16 + aRow;
                const int c = ks + aColOff;
                ldsm_x4(ah[mt], &sA[buf][0][r][c]);
                ldsm_x4(al[mt], &sA[buf][1][r][c]);
            }
            uint32_t bh[4][2], bl[4][2];
            #pragma unroll
            for (int np = 0; np < 2; np++) {
                const int n0 = wn * 32 + np * 16 + bRow;
                const int c = ks + bColOff;
                uint32_t t[4];
                ldsm_x4(t, &sB[buf][0][n0][c]);
                bh[np * 2][0] = t[0];     bh[np * 2][1] = t[1];
                bh[np * 2 + 1][0] = t[2]; bh[np * 2 + 1][1] = t[3];
                ldsm_x4(t, &sB[buf][1][n0][c]);
                bl[np * 2][0] = t[0];     bl[np * 2][1] = t[1];
                bl[np * 2 + 1][0] = t[2]; bl[np * 2 + 1][1] = t[3];
            }
            #pragma unroll
            for (int mt = 0; mt < 2; mt++)
                #pragma unroll
                for (int nt = 0; nt < 4; nt++) {
                    mma_bf16(acc[mt][nt], ah[mt], bh[nt]);
                    mma_bf16(acc[mt][nt], al[mt], bh[nt]);
                    mma_bf16(acc[mt][nt], ah[mt], bl[nt]);
                }
        }
        __syncthreads();
    }

    const int g  = lane >> 2;
    const int t4 = lane & 3;
    float* C = P.C[sel];
    const int Cld = P.Cld[sel];
    const float* bias = P.bias[sel];
    #pragma unroll
    for (int mt = 0; mt < 2; mt++) {
        const int r0 = rowBase + wm * 32 + mt * 16 + g;
        #pragma unroll
        for (int nt = 0; nt < 4; nt++) {
            const int cc = colBase + wn * 32 + nt * 8 + 2 * t4;
            const float b0 = __ldg(&bias[cc]);
            const float b1 = __ldg(&bias[cc + 1]);
            if (r0 < Nrows) {
                float2 v = make_float2(acc[mt][nt][0] + b0, acc[mt][nt][1] + b1);
                *reinterpret_cast<float2*>(&C[(size_t)r0 * Cld + cc]) = v;
            }
            if (r0 + 8 < Nrows) {
                float2 v = make_float2(acc[mt][nt][2] + b0, acc[mt][nt][3] + b1);
                *reinterpret_cast<float2*>(&C[(size_t)(r0 + 8) * Cld + cc]) = v;
            }
        }
    }
}

// ===========================================================================
// leaky-relu helper
// ===========================================================================
__device__ __forceinline__ float lrelu(float v) { return (v > 0.f) ? v : SLOPE * v; }

// ===========================================================================
// Aggregation v2, layers 0/1 (H=4, D=64): 8 lanes per edge, 4 edges/warp.
// warp = head; lane = grp*8 + sl; lane owns dims [sl*8, sl*8+8).
// Intra-group reduce: 3 shuffles (serving 4 edges per instruction).
// Cross-group combine once at the end (xor 8, 16).
// ===========================================================================
template <int RES, int WRITE_F32>
__global__ __launch_bounds__(128) void gat_agg_h4d64_kernel(
    const int* __restrict__ rowptr, const int* __restrict__ col,
    const float* __restrict__ FS, const float* __restrict__ FD,
    const float* __restrict__ attn,
    const float* __restrict__ resid, float* __restrict__ out,
    __nv_bfloat16* __restrict__ AH, __nv_bfloat16* __restrict__ AL)
{
    const int node = blockIdx.x;
    const int w    = threadIdx.x >> 5;     // head
    const int lane = threadIdx.x & 31;
    const int grp  = lane >> 3;
    const int sl   = lane & 7;

    const int off = w * 64 + sl * 8;       // this lane's 8 dims
    const float4 fdA = *reinterpret_cast<const float4*>(&FD[(size_t)node * 256 + off]);
    const float4 fdB = *reinterpret_cast<const float4*>(&FD[(size_t)node * 256 + off + 4]);
    const float4 atA = *reinterpret_cast<const float4*>(&attn[off]);
    const float4 atB = *reinterpret_cast<const float4*>(&attn[off + 4]);

    float s[8] = {0.f, 0.f, 0.f, 0.f, 0.f, 0.f, 0.f, 0.f};
    float den = 0.f;

    const int p0 = rowptr[node], pEnd = rowptr[node + 1];

    auto edge = [&](int myp) {
        const int sn = col[myp];
        const float* fr = &FS[(size_t)sn * 256 + off];
        float4 fA = *reinterpret_cast<const float4*>(fr);
        float4 fB = *reinterpret_cast<const float4*>(fr + 4);
        float t = lrelu(fA.x + fdA.x) * atA.x + lrelu(fA.y + fdA.y) * atA.y
                + lrelu(fA.z + fdA.z) * atA.z + lrelu(fA.w + fdA.w) * atA.w
                + lrelu(fB.x + fdB.x) * atB.x + lrelu(fB.y + fdB.y) * atB.y
                + lrelu(fB.z + fdB.z) * atB.z + lrelu(fB.w + fdB.w) * atB.w;
        t += __shfl_xor_sync(0xffffffffu, t, 1);
        t += __shfl_xor_sync(0xffffffffu, t, 2);
        t += __shfl_xor_sync(0xffffffffu, t, 4);
        const float ex = __expf(t);
        den += ex;
        s[0] += fA.x * ex; s[1] += fA.y * ex; s[2] += fA.z * ex; s[3] += fA.w * ex;
        s[4] += fB.x * ex; s[5] += fB.y * ex; s[6] += fB.z * ex; s[7] += fB.w * ex;
    };

    int p = p0;
    for (; p + 8 <= pEnd; p += 8) {      // all lanes' edges valid
        edge(p + grp);
        edge(p + 4 + grp);
    }
    for (; p < pEnd; p += 4) {           // masked tail
        const int myp = p + grp;
        const bool valid = (myp < pEnd);
        const int sn = valid ? col[myp] : 0;
        const float* fr = &FS[(size_t)sn * 256 + off];
        float4 fA = *reinterpret_cast<const float4*>(fr);
        float4 fB = *reinterpret_cast<const float4*>(fr + 4);
        float t = lrelu(fA.x + fdA.x) * atA.x + lrelu(fA.y + fdA.y) * atA.y
                + lrelu(fA.z + fdA.z) * atA.z + lrelu(fA.w + fdA.w) * atA.w
                + lrelu(fB.x + fdB.x) * atB.x + lrelu(fB.y + fdB.y) * atB.y
                + lrelu(fB.z + fdB.z) * atB.z + lrelu(fB.w + fdB.w) * atB.w;
        t += __shfl_xor_sync(0xffffffffu, t, 1);
        t += __shfl_xor_sync(0xffffffffu, t, 2);
        t += __shfl_xor_sync(0xffffffffu, t, 4);
        const float ex = valid ? __expf(t) : 0.f;
        den += ex;
        s[0] += fA.x * ex; s[1] += fA.y * ex; s[2] += fA.z * ex; s[3] += fA.w * ex;
        s[4] += fB.x * ex; s[5] += fB.y * ex; s[6] += fB.z * ex; s[7] += fB.w * ex;
    }

    // cross-group combine
    #pragma unroll
    for (int o = 8; o <= 16; o <<= 1) {
        den += __shfl_xor_sync(0xffffffffu, den, o);
        #pragma unroll
        for (int k = 0; k < 8; k++) s[k] += __shfl_xor_sync(0xffffffffu, s[k], o);
    }

    if (grp == 0) {
        const float inv = (den > 0.f) ? (1.f / den) : 0.f;
        float o_[8];
        #pragma unroll
        for (int k = 0; k < 8; k++) {
            float v = s[k] * inv;
            if (RES) v += resid[(size_t)node * 256 + off + k];
            o_[k] = (v > 0.f) ? v : expm1f(v);
        }
        if (WRITE_F32) {
            *reinterpret_cast<float4*>(&out[(size_t)node * 256 + off]) =
                make_float4(o_[0], o_[1], o_[2], o_[3]);
            *reinterpret_cast<float4*>(&out[(size_t)node * 256 + off + 4]) =
                make_float4(o_[4], o_[5], o_[6], o_[7]);
        }
        #pragma unroll
        for (int k = 0; k < 8; k++) {
            __nv_bfloat16 h = __float2bfloat16(o_[k]);
            AH[(size_t)node * 256 + off + k] = h;
            AL[(size_t)node * 256 + off + k] = __float2bfloat16(o_[k] - __bfloat162float(h));
        }
    }
}

// ===========================================================================
// Aggregation v2, layer 2 (H=6, D=32): 8 lanes/edge, lane owns 4 dims.
// + head mean + head-averaged residual (resm [N x 64], first 32 cols valid).
// ===========================================================================
__global__ __launch_bounds__(192) void gat_agg_l2_kernel(
    const int* __restrict__ rowptr, const int* __restrict__ col,
    const float* __restrict__ FS, const float* __restrict__ FD,
    const float* __restrict__ attn,
    const float* __restrict__ resm, float* __restrict__ out)
{
    __shared__ float sm[192];
    const int node = blockIdx.x;
    const int w    = threadIdx.x / 32;     // head 0..5
    const int lane = threadIdx.x & 31;
    const int grp  = lane >> 3;
    const int sl   = lane & 7;

    const int off = w * 32 + sl * 4;       // this lane's 4 dims
    const float4 fd4 = *reinterpret_cast<const float4*>(&FD[(size_t)node * 192 + off]);
    const float4 at4 = *reinterpret_cast<const float4*>(&attn[off]);

    float s[4] = {0.f, 0.f, 0.f, 0.f};
    float den = 0.f;

    const int p0 = rowptr[node], pEnd = rowptr[node + 1];

    int p = p0;
    for (; p + 8 <= pEnd; p += 8) {
        #pragma unroll
        for (int u = 0; u < 2; u++) {
            const int sn = col[p + u * 4 + grp];
            float4 f = *reinterpret_cast<const float4*>(&FS[(size_t)sn * 192 + off]);
            float t = lrelu(f.x + fd4.x) * at4.x + lrelu(f.y + fd4.y) * at4.y
                    + lrelu(f.z + fd4.z) * at4.z + lrelu(f.w + fd4.w) * at4.w;
            t += __shfl_xor_sync(0xffffffffu, t, 1);
            t += __shfl_xor_sync(0xffffffffu, t, 2);
            t += __shfl_xor_sync(0xffffffffu, t, 4);
            const float ex = __expf(t);
            den += ex;
            s[0] += f.x * ex; s[1] += f.y * ex; s[2] += f.z * ex; s[3] += f.w * ex;
        }
    }
    for (; p < pEnd; p += 4) {
        const int myp = p + grp;
        const bool valid = (myp < pEnd);
        const int sn = valid ? col[myp] : 0;
        float4 f = *reinterpret_cast<const float4*>(&FS[(size_t)sn * 192 + off]);
        float t = lrelu(f.x + fd4.x) * at4.x + lrelu(f.y + fd4.y) * at4.y
                + lrelu(f.z + fd4.z) * at4.z + lrelu(f.w + fd4.w) * at4.w;
        t += __shfl_xor_sync(0xffffffffu, t, 1);
        t += __shfl_xor_sync(0xffffffffu, t, 2);
        t += __shfl_xor_sync(0xffffffffu, t, 4);
        const float ex = valid ? __expf(t) : 0.f;
        den += ex;
        s[0] += f.x * ex; s[1] += f.y * ex; s[2] += f.z * ex; s[3] += f.w * ex;
    }

    #pragma unroll
    for (int o = 8; o <= 16; o <<= 1) {
        den += __shfl_xor_sync(0xffffffffu, den, o);
        #pragma unroll
        for (int k = 0; k < 4; k++) s[k] += __shfl_xor_sync(0xffffffffu, s[k], o);
    }

    if (grp == 0) {
        const float inv = (den > 0.f) ? (1.f / den) : 0.f;
        #pragma unroll
        for (int k = 0; k < 4; k++) sm[off + k] = s[k] * inv;
    }
    __syncthreads();

    if (w == 0) {
        float m = 0.f;
        #pragma unroll
        for (int h = 0; h < 6; h++) m += sm[h * 32 + lane];
        out[(size_t)node * 32 + lane] = m * (1.f / 6.f) + resm[(size_t)node * 64 + lane];
    }
}

// ===========================================================================
// Host driver
// ===========================================================================
extern "C" void kernel_launch(void* const* d_in, const int* in_sizes, int n_in,
                              void* d_out, int out_size)
{
    const float* x   = (const float*)d_in[0];
    const int*   src = (const int*)d_in[1];
    const int*   dst = (const int*)d_in[2];
    const float* W0s = (const float*)d_in[3];
    const float* b0s = (const float*)d_in[4];
    const float* W0d = (const float*)d_in[5];
    const float* b0d = (const float*)d_in[6];
    const float* a0  = (const float*)d_in[7];
    const float* W1s = (const float*)d_in[8];
    const float* b1s = (const float*)d_in[9];
    const float* W1d = (const float*)d_in[10];
    const float* b1d = (const float*)d_in[11];
    const float* a1  = (const float*)d_in[12];
    const float* W2s = (const float*)d_in[13];
    const float* b2s = (const float*)d_in[14];
    const float* W2d = (const float*)d_in[15];
    const float* b2d = (const float*)d_in[16];
    const float* a2  = (const float*)d_in[17];
    const float* Wr2 = (const float*)d_in[18];
    const float* br2 = (const float*)d_in[19];

    const int N = in_sizes[0] / 128;
    const int E = in_sizes[1];

    float *FS, *FD, *HA, *BR2M;
    __nv_bfloat16 *AH, *AL, *WH, *WL;
    int *CNT, *ROWPTR, *CURS, *COL;
    cudaGetSymbolAddress((void**)&FS, g_FS);
    cudaGetSymbolAddress((void**)&FD, g_FD);
    cudaGetSymbolAddress((void**)&HA, g_HA);
    cudaGetSymbolAddress((void**)&BR2M, g_BR2M);
    cudaGetSymbolAddress((void**)&AH, g_AH);
    cudaGetSymbolAddress((void**)&AL, g_AL);
    cudaGetSymbolAddress((void**)&WH, g_WH);
    cudaGetSymbolAddress((void**)&WL, g_WL);
    cudaGetSymbolAddress((void**)&CNT, g_CNT);
    cudaGetSymbolAddress((void**)&ROWPTR, g_ROWPTR);
    cudaGetSymbolAddress((void**)&CURS, g_CURS);
    cudaGetSymbolAddress((void**)&COL, g_COL);

    float* out = (float*)d_out;

    const int TB = 256;
    const int mTiles = cdiv(N, 128);

    // launch order: wconv(1) conv_x(2) hist(3) scan(4) gemm0(5) fill(6) ...
    {
        WcP wp;
        wp.W[0] = W0s; wp.W[1] = W0d; wp.W[2] = W1s; wp.W[3] = W1d;
        wp.W[4] = W2s; wp.W[5] = W2d; wp.Wr2 = Wr2; wp.br2 = br2;
        wconv_kernel<<<cdiv(WT_TOTAL, TB), TB>>>(wp, WH, WL, BR2M);
    }
    conv_x_kernel<<<cdiv(N * 128, TB), TB>>>(x, AH, AL, N * 128);
    hist_kernel<<<cdiv(E, TB), TB>>>(dst, CNT, E);
    scan_kernel<<<1, 1024>>>(CNT, ROWPTR, CURS, N);

    // ---------------- Layer 0 GEMM: K=128 -> FS, FD ----------------
    {
        MmaP P;
        for (int i = 0; i < 8; i++) { P.selMap[i] = i >> 2; P.colMap[i] = (i & 3) * 64; }
        P.woff[0] = 0;     P.bias[0] = b0s; P.C[0] = FS; P.Cld[0] = 256;
        P.woff[1] = 32768; P.bias[1] = b0d; P.C[1] = FD; P.Cld[1] = 256;
        P.woff[2] = 0;     P.bias[2] = b0s; P.C[2] = FS; P.Cld[2] = 256;
        dim3 grid(mTiles, 8);
        gemm_mma_kernel<<<grid, 256>>>(AH, AL, WH, WL, P, N, 128);
    }

    fill_kernel<<<cdiv(E, TB), TB>>>(src, dst, CURS, COL, E);

    gat_agg_h4d64_kernel<0, 1><<<N, 128>>>(ROWPTR, COL, FS, FD, a0, nullptr, HA, AH, AL);

    // ---------------- Layer 1: K=256 -> FS, FD ----------------
    {
        MmaP P;
        for (int i = 0; i < 8; i++) { P.selMap[i] = i >> 2; P.colMap[i] = (i & 3) * 64; }
        P.woff[0] = 65536;  P.bias[0] = b1s; P.C[0] = FS; P.Cld[0] = 256;
        P.woff[1] = 131072; P.bias[1] = b1d; P.C[1] = FD; P.Cld[1] = 256;
        P.woff[2] = 0;      P.bias[2] = b1s; P.C[2] = FS; P.Cld[2] = 256;
        dim3 grid(mTiles, 8);
        gemm_mma_kernel<<<grid, 256>>>(AH, AL, WH, WL, P, N, 256);
    }
    gat_agg_h4d64_kernel<1, 0><<<N, 128>>>(ROWPTR, COL, FS, FD, a1, HA, nullptr, AH, AL);

    // ---------------- Layer 2: K=256 -> FS, FD (192) + resm (64) ------
    {
        MmaP P;
        const int sm_[7] = {0, 0, 0, 1, 1, 1, 2};
        const int cm_[7] = {0, 64, 128, 0, 64, 128, 0};
        for (int i = 0; i < 7; i++) { P.selMap[i] = sm_[i]; P.colMap[i] = cm_[i]; }
        P.selMap[7] = 0; P.colMap[7] = 0;
        P.woff[0] = 196608; P.bias[0] = b2s;  P.C[0] = FS; P.Cld[0] = 192;
        P.woff[1] = 245760; P.bias[1] = b2d;  P.C[1] = FD; P.Cld[1] = 192;
        P.woff[2] = 294912; P.bias[2] = BR2M; P.C[2] = HA; P.Cld[2] = 64;
        dim3 grid(mTiles, 7);
        gemm_mma_kernel<<<grid, 256>>>(AH, AL, WH, WL, P, N, 256);
    }
    gat_agg_l2_kernel<<<N, 192>>>(ROWPTR, COL, FS, FD, a2, HA, out);
}

// round 13
// speedup vs baseline: 1.1313x; 1.0633x over previous
#include <cuda_runtime.h>
#include <cuda_bf16.h>
#include <cstdint>

// ===========================================================================
// GATv2, 3 layers. N=20000, E=320000.
// CSR gather aggregation + split-bf16 mma.sync GEMMs (R10 config)
// + hierarchical 2-kernel CSR prefix scan.
// ===========================================================================

#define N_MAX   20000
#define NPAD    20096            // 157 * 128
#define E_MAX   320000
#define SLOPE   0.2f
#define SCAN_B  512
#define SCAN_G  40               // 40 * 512 >= 20000

__device__ __align__(16) float g_FS[N_MAX * 256];
__device__ __align__(16) float g_FD[N_MAX * 256];
__device__ __align__(16) float g_HA[N_MAX * 256];
__device__ __align__(16) __nv_bfloat16 g_AH[NPAD * 256];
__device__ __align__(16) __nv_bfloat16 g_AL[NPAD * 256];
#define WT_TOTAL 311296
__device__ __align__(16) __nv_bfloat16 g_WH[WT_TOTAL];
__device__ __align__(16) __nv_bfloat16 g_WL[WT_TOTAL];
__device__ __align__(16) float g_BR2M[64];
__device__ int g_CNT[N_MAX];
__device__ int g_ROWPTR[N_MAX + 1];
__device__ int g_CURS[N_MAX];
__device__ int g_COL[E_MAX];
__device__ int g_BLKSUM[SCAN_G];

static inline int cdiv(int a, int b) { return (a + b - 1) / b; }

// ===========================================================================
// CSR build
// ===========================================================================
__global__ void hist_kernel(const int* __restrict__ dst, int* __restrict__ cnt, int E) {
    int e = blockIdx.x * blockDim.x + threadIdx.x;
    if (e < E) atomicAdd(&cnt[dst[e]], 1);
}

// Stage 1: per-block exclusive scan of cnt -> rowptr (partial), block sums,
// and re-zero cnt for the next graph replay.
__global__ __launch_bounds__(SCAN_B) void scan_blk_kernel(
    int* __restrict__ cnt, int* __restrict__ rowptr,
    int* __restrict__ blksum, int n)
{
    __shared__ int sm[SCAN_B];
    const int t = threadIdx.x;
    const int idx = blockIdx.x * SCAN_B + t;
    int v = (idx < n) ? cnt[idx] : 0;
    sm[t] = v;
    __syncthreads();
    for (int off = 1; off < SCAN_B; off <<= 1) {
        int u = (t >= off) ? sm[t - off] : 0;
        __syncthreads();
        sm[t] += u;
        __syncthreads();
    }
    if (idx < n) {
        rowptr[idx] = sm[t] - v;   // exclusive within block
        cnt[idx] = 0;
    }
    if (t == SCAN_B - 1) blksum[blockIdx.x] = sm[t];
}

// Stage 2: add block-prefix offsets; write curs and rowptr[n].
__global__ __launch_bounds__(SCAN_B) void scan_fix_kernel(
    const int* __restrict__ blksum, int* __restrict__ rowptr,
    int* __restrict__ curs, int n)
{
    __shared__ int soff;
    const int b = blockIdx.x;
    const int t = threadIdx.x;
    if (t == 0) {
        int o = 0;
        for (int i = 0; i < b; i++) o += blksum[i];
        soff = o;
        if (b == gridDim.x - 1) rowptr[n] = o + blksum[b];
    }
    __syncthreads();
    const int off = soff;
    const int idx = b * SCAN_B + t;
    if (idx < n) {
        int r = rowptr[idx] + off;
        rowptr[idx] = r;
        curs[idx] = r;
    }
}

__global__ void fill_kernel(const int* __restrict__ src, const int* __restrict__ dst,
                            int* __restrict__ curs, int* __restrict__ col, int E) {
    int e = blockIdx.x * blockDim.x + threadIdx.x;
    if (e < E) {
        int pos = atomicAdd(&curs[dst[e]], 1);
        col[pos] = src[e];
    }
}

// ===========================================================================
// Weight conversion: transpose + bf16 hi/lo split (packed; j=6 = head-mean Wr2)
// ===========================================================================
struct WcP { const float* W[6]; const float* Wr2; const float* br2; };

__global__ void wconv_kernel(WcP P, __nv_bfloat16* __restrict__ WH,
                             __nv_bfloat16* __restrict__ WL, float* __restrict__ bm) {
    int i = blockIdx.x * blockDim.x + threadIdx.x;
    if (i < 64) {
        float v = 0.f;
        if (i < 32) {
            #pragma unroll
            for (int h = 0; h < 6; h++) v += P.br2[h * 32 + i];
            v *= (1.f / 6.f);
        }
        bm[i] = v;
    }
    if (i >= WT_TOTAL) return;
    const int offs[8] = {0, 32768, 65536, 131072, 196608, 245760, 294912, 311296};
    const int Ks[7]   = {128, 128, 256, 256, 256, 256, 256};
    const int Ms[7]   = {256, 256, 256, 256, 192, 192, 64};
    int j = 0;
    #pragma unroll
    for (int q = 1; q < 7; q++) if (i >= offs[q]) j = q;
    int local = i - offs[j];
    int K = Ks[j];
    int n = local / K, k = local % K;
    float v;
    if (j < 6) {
        v = P.W[j][(size_t)k * Ms[j] + n];
    } else {
        v = 0.f;
        if (n < 32) {
            #pragma unroll
            for (int h = 0; h < 6; h++) v += P.Wr2[(size_t)k * 192 + h * 32 + n];
            v *= (1.f / 6.f);
        }
    }
    __nv_bfloat16 h = __float2bfloat16(v);
    WH[i] = h;
    WL[i] = __float2bfloat16(v - __bfloat162float(h));
}

__global__ void conv_x_kernel(const float* __restrict__ x,
                              __nv_bfloat16* __restrict__ AH,
                              __nv_bfloat16* __restrict__ AL, int n) {
    int i = blockIdx.x * blockDim.x + threadIdx.x;
    if (i >= n) return;
    float v = x[i];
    __nv_bfloat16 h = __float2bfloat16(v);
    AH[i] = h;
    AL[i] = __float2bfloat16(v - __bfloat162float(h));
}

// ===========================================================================
// Split-bf16 mma GEMM (R10 config).
// CTA 128x64, 256 thr / 8 warps (4m x 2n), warp tile 32x32, K staged 32.
// cp.async.cg double-buffered smem; ldmatrix frag loads.
// D = Ah*Bh + Al*Bh + Ah*Bl (fp32 accum).
// ===========================================================================
#define SPAD 40

struct MmaP {
    int   selMap[8];
    int   colMap[8];
    int   woff[3];
    const float* bias[3];
    float* C[3];
    int   Cld[3];
};

__device__ __forceinline__ void mma_bf16(float d[4], const uint32_t a[4],
                                         const uint32_t b[2]) {
    asm volatile(
        "mma.sync.aligned.m16n8k16.row.col.f32.bf16.bf16.f32 "
        "{%0,%1,%2,%3}, {%4,%5,%6,%7}, {%8,%9}, {%0,%1,%2,%3};"
        : "+f"(d[0]), "+f"(d[1]), "+f"(d[2]), "+f"(d[3])
        : "r"(a[0]), "r"(a[1]), "r"(a[2]), "r"(a[3]), "r"(b[0]), "r"(b[1]));
}

__device__ __forceinline__ void ldsm_x4(uint32_t r[4], const __nv_bfloat16* p) {
    uint32_t a = (uint32_t)__cvta_generic_to_shared(p);
    asm volatile("ldmatrix.sync.aligned.m8n8.x4.shared.b16 {%0,%1,%2,%3}, [%4];"
                 : "=r"(r[0]), "=r"(r[1]), "=r"(r[2]), "=r"(r[3]) : "r"(a));
}

__device__ __forceinline__ void cp16(void* smem, const void* g) {
    uint32_t s = (uint32_t)__cvta_generic_to_shared(smem);
    asm volatile("cp.async.cg.shared.global [%0], [%1], 16;" :: "r"(s), "l"(g));
}
#define CP_COMMIT() asm volatile("cp.async.commit_group;" ::: "memory")

__global__ __launch_bounds__(256) void gemm_mma_kernel(
    const __nv_bfloat16* __restrict__ AH, const __nv_bfloat16* __restrict__ AL,
    const __nv_bfloat16* __restrict__ WHg, const __nv_bfloat16* __restrict__ WLg,
    MmaP P, int Nrows, int K)
{
    __shared__ __align__(16) __nv_bfloat16 sA[2][2][128][SPAD];
    __shared__ __align__(16) __nv_bfloat16 sB[2][2][64][SPAD];

    const int tid  = threadIdx.x;
    const int wid  = tid >> 5;
    const int lane = tid & 31;
    const int wm   = wid & 3;
    const int wn   = wid >> 2;

    const int sel     = P.selMap[blockIdx.y];
    const int colBase = P.colMap[blockIdx.y];
    const int rowBase = blockIdx.x * 128;

    const __nv_bfloat16* __restrict__ WH = WHg + P.woff[sel];
    const __nv_bfloat16* __restrict__ WL = WLg + P.woff[sel];

    float acc[2][4][4];
    #pragma unroll
    for (int i = 0; i < 2; i++)
        #pragma unroll
        for (int j = 0; j < 4; j++)
            #pragma unroll
            for (int q = 0; q < 4; q++) acc[i][j][q] = 0.f;

    const int aRow = (lane & 15);
    const int aColOff = ((lane >> 4) << 3);
    const int bRow = (lane & 7) | ((lane & 16) >> 1);
    const int bColOff = (lane & 8);

    const int nStages = K / 32;

    auto fill = [&](int s, int buf) {
        const int kB = s * 32;
        #pragma unroll
        for (int i = 0; i < 2; i++) {
            int j = tid * 2 + i;
            int r = j >> 2, sl = j & 3;
            cp16(&sA[buf][0][r][sl * 8], &AH[(size_t)(rowBase + r) * K + kB + sl * 8]);
            cp16(&sA[buf][1][r][sl * 8], &AL[(size_t)(rowBase + r) * K + kB + sl * 8]);
        }
        {
            int r = tid >> 2, sl = tid & 3;
            cp16(&sB[buf][0][r][sl * 8], &WH[(size_t)(colBase + r) * K + kB + sl * 8]);
            cp16(&sB[buf][1][r][sl * 8], &WL[(size_t)(colBase + r) * K + kB + sl * 8]);
        }
        CP_COMMIT();
    };

    fill(0, 0);

    for (int s = 0; s < nStages; s++) {
        const int buf = s & 1;
        if (s + 1 < nStages) {
            fill(s + 1, buf ^ 1);
            asm volatile("cp.async.wait_group 1;" ::: "memory");
        } else {
            asm volatile("cp.async.wait_group 0;" ::: "memory");
        }
        __syncthreads();

        #pragma unroll
        for (int ks = 0; ks < 32; ks += 16) {
            uint32_t ah[2][4], al[2][4];
            #pragma unroll
            for (int mt = 0; mt < 2; mt++) {
                const int r = wm * 32 + mt * 16 + aRow;
                const int c = ks + aColOff;
                ldsm_x4(ah[mt], &sA[buf][0][r][c]);
                ldsm_x4(al[mt], &sA[buf][1][r][c]);
            }
            uint32_t bh[4][2], bl[4][2];
            #pragma unroll
            for (int np = 0; np < 2; np++) {
                const int n0 = wn * 32 + np * 16 + bRow;
                const int c = ks + bColOff;
                uint32_t t[4];
                ldsm_x4(t, &sB[buf][0][n0][c]);
                bh[np * 2][0] = t[0];     bh[np * 2][1] = t[1];
                bh[np * 2 + 1][0] = t[2]; bh[np * 2 + 1][1] = t[3];
                ldsm_x4(t, &sB[buf][1][n0][c]);
                bl[np * 2][0] = t[0];     bl[np * 2][1] = t[1];
                bl[np * 2 + 1][0] = t[2]; bl[np * 2 + 1][1] = t[3];
            }
            #pragma unroll
            for (int mt = 0; mt < 2; mt++)
                #pragma unroll
                for (int nt = 0; nt < 4; nt++) {
                    mma_bf16(acc[mt][nt], ah[mt], bh[nt]);
                    mma_bf16(acc[mt][nt], al[mt], bh[nt]);
                    mma_bf16(acc[mt][nt], ah[mt], bl[nt]);
                }
        }
        __syncthreads();
    }

    const int g  = lane >> 2;
    const int t4 = lane & 3;
    float* C = P.C[sel];
    const int Cld = P.Cld[sel];
    const float* bias = P.bias[sel];
    #pragma unroll
    for (int mt = 0; mt < 2; mt++) {
        const int r0 = rowBase + wm * 32 + mt * 16 + g;
        #pragma unroll
        for (int nt = 0; nt < 4; nt++) {
            const int cc = colBase + wn * 32 + nt * 8 + 2 * t4;
            const float b0 = __ldg(&bias[cc]);
            const float b1 = __ldg(&bias[cc + 1]);
            if (r0 < Nrows) {
                float2 v = make_float2(acc[mt][nt][0] + b0, acc[mt][nt][1] + b1);
                *reinterpret_cast<float2*>(&C[(size_t)r0 * Cld + cc]) = v;
            }
            if (r0 + 8 < Nrows) {
                float2 v = make_float2(acc[mt][nt][2] + b0, acc[mt][nt][3] + b1);
                *reinterpret_cast<float2*>(&C[(size_t)(r0 + 8) * Cld + cc]) = v;
            }
        }
    }
}

// ===========================================================================
// Aggregation, layers 0/1 (H=4, D=64), unroll 4; bf16 hi/lo epilogue.
// ===========================================================================
template <int RES, int WRITE_F32>
__global__ __launch_bounds__(128) void gat_agg_h4d64_kernel(
    const int* __restrict__ rowptr, const int* __restrict__ col,
    const float* __restrict__ FS, const float* __restrict__ FD,
    const float* __restrict__ attn,
    const float* __restrict__ resid, float* __restrict__ out,
    __nv_bfloat16* __restrict__ AH, __nv_bfloat16* __restrict__ AL)
{
    const int node = blockIdx.x;
    const int w = threadIdx.x >> 5;
    const int lane = threadIdx.x & 31;

    const int off = w * 64 + lane;
    const float fd0 = FD[(size_t)node * 256 + off];
    const float fd1 = FD[(size_t)node * 256 + off + 32];
    const float at0 = __ldg(&attn[w * 64 + lane]);
    const float at1 = __ldg(&attn[w * 64 + lane + 32]);

    float s0 = 0.f, s1 = 0.f, den = 0.f;

    int p = rowptr[node];
    const int pEnd = rowptr[node + 1];

    for (; p + 4 <= pEnd; p += 4) {
        int sn0 = col[p], sn1 = col[p + 1], sn2 = col[p + 2], sn3 = col[p + 3];
        float f00 = FS[(size_t)sn0 * 256 + off], f01 = FS[(size_t)sn0 * 256 + off + 32];
        float f10 = FS[(size_t)sn1 * 256 + off], f11 = FS[(size_t)sn1 * 256 + off + 32];
        float f20 = FS[(size_t)sn2 * 256 + off], f21 = FS[(size_t)sn2 * 256 + off + 32];
        float f30 = FS[(size_t)sn3 * 256 + off], f31 = FS[(size_t)sn3 * 256 + off + 32];

        float v, t0, t1, t2, t3;
        v = f00 + fd0; v = (v > 0.f) ? v : SLOPE * v; t0  = v * at0;
        v = f01 + fd1; v = (v > 0.f) ? v : SLOPE * v; t0 += v * at1;
        v = f10 + fd0; v = (v > 0.f) ? v : SLOPE * v; t1  = v * at0;
        v = f11 + fd1; v = (v > 0.f) ? v : SLOPE * v; t1 += v * at1;
        v = f20 + fd0; v = (v > 0.f) ? v : SLOPE * v; t2  = v * at0;
        v = f21 + fd1; v = (v > 0.f) ? v : SLOPE * v; t2 += v * at1;
        v = f30 + fd0; v = (v > 0.f) ? v : SLOPE * v; t3  = v * at0;
        v = f31 + fd1; v = (v > 0.f) ? v : SLOPE * v; t3 += v * at1;

        #pragma unroll
        for (int o = 16; o > 0; o >>= 1) {
            t0 += __shfl_xor_sync(0xffffffffu, t0, o);
            t1 += __shfl_xor_sync(0xffffffffu, t1, o);
            t2 += __shfl_xor_sync(0xffffffffu, t2, o);
            t3 += __shfl_xor_sync(0xffffffffu, t3, o);
        }
        float e0 = __expf(t0), e1 = __expf(t1), e2 = __expf(t2), e3 = __expf(t3);
        den += (e0 + e1) + (e2 + e3);
        s0 += f00 * e0 + f10 * e1 + f20 * e2 + f30 * e3;
        s1 += f01 * e0 + f11 * e1 + f21 * e2 + f31 * e3;
    }
    for (; p < pEnd; p++) {
        int sn = col[p];
        float f0 = FS[(size_t)sn * 256 + off];
        float f1 = FS[(size_t)sn * 256 + off + 32];
        float v0 = f0 + fd0; v0 = (v0 > 0.f) ? v0 : SLOPE * v0;
        float v1 = f1 + fd1; v1 = (v1 > 0.f) ? v1 : SLOPE * v1;
        float t = v0 * at0 + v1 * at1;
        #pragma unroll
        for (int o = 16; o > 0; o >>= 1) t += __shfl_xor_sync(0xffffffffu, t, o);
        float ex = __expf(t);
        den += ex; s0 += f0 * ex; s1 += f1 * ex;
    }

    const float inv = (den > 0.f) ? (1.f / den) : 0.f;
    float o0 = s0 * inv;
    float o1 = s1 * inv;
    if (RES) {
        o0 += resid[(size_t)node * 256 + off];
        o1 += resid[(size_t)node * 256 + off + 32];
    }
    o0 = (o0 > 0.f) ? o0 : expm1f(o0);
    o1 = (o1 > 0.f) ? o1 : expm1f(o1);
    if (WRITE_F32) {
        out[(size_t)node * 256 + off]      = o0;
        out[(size_t)node * 256 + off + 32] = o1;
    }
    __nv_bfloat16 h0 = __float2bfloat16(o0);
    __nv_bfloat16 h1 = __float2bfloat16(o1);
    AH[(size_t)node * 256 + off]      = h0;
    AH[(size_t)node * 256 + off + 32] = h1;
    AL[(size_t)node * 256 + off]      = __float2bfloat16(o0 - __bfloat162float(h0));
    AL[(size_t)node * 256 + off + 32] = __float2bfloat16(o1 - __bfloat162float(h1));
}

// ===========================================================================
// Aggregation, layer 2 (H=6, D=32) + head mean + head-averaged residual.
// ===========================================================================
__global__ __launch_bounds__(192) void gat_agg_l2_kernel(
    const int* __restrict__ rowptr, const int* __restrict__ col,
    const float* __restrict__ FS, const float* __restrict__ FD,
    const float* __restrict__ attn,
    const float* __restrict__ resm, float* __restrict__ out)
{
    __shared__ float sm[192];
    const int node = blockIdx.x;
    const int w = threadIdx.x / 32;
    const int lane = threadIdx.x & 31;

    const int off = w * 32 + lane;
    const float fd = FD[(size_t)node * 192 + off];
    const float at = __ldg(&attn[off]);

    float s = 0.f, den = 0.f;

    int p = rowptr[node];
    const int pEnd = rowptr[node + 1];

    for (; p + 4 <= pEnd; p += 4) {
        int sn0 = col[p], sn1 = col[p + 1], sn2 = col[p + 2], sn3 = col[p + 3];
        float f0 = FS[(size_t)sn0 * 192 + off];
        float f1 = FS[(size_t)sn1 * 192 + off];
        float f2 = FS[(size_t)sn2 * 192 + off];
        float f3 = FS[(size_t)sn3 * 192 + off];
        float v, t0, t1, t2, t3;
        v = f0 + fd; v = (v > 0.f) ? v : SLOPE * v; t0 = v * at;
        v = f1 + fd; v = (v > 0.f) ? v : SLOPE * v; t1 = v * at;
        v = f2 + fd; v = (v > 0.f) ? v : SLOPE * v; t2 = v * at;
        v = f3 + fd; v = (v > 0.f) ? v : SLOPE * v; t3 = v * at;
        #pragma unroll
        for (int o = 16; o > 0; o >>= 1) {
            t0 += __shfl_xor_sync(0xffffffffu, t0, o);
            t1 += __shfl_xor_sync(0xffffffffu, t1, o);
            t2 += __shfl_xor_sync(0xffffffffu, t2, o);
            t3 += __shfl_xor_sync(0xffffffffu, t3, o);
        }
        float e0 = __expf(t0), e1 = __expf(t1), e2 = __expf(t2), e3 = __expf(t3);
        den += (e0 + e1) + (e2 + e3);
        s += f0 * e0 + f1 * e1 + f2 * e2 + f3 * e3;
    }
    for (; p < pEnd; p++) {
        int sn = col[p];
        float f = FS[(size_t)sn * 192 + off];
        float v = f + fd; v = (v > 0.f) ? v : SLOPE * v;
        float t = v * at;
        #pragma unroll
        for (int o = 16; o > 0; o >>= 1) t += __shfl_xor_sync(0xffffffffu, t, o);
        float ex = __expf(t);
        den += ex; s += f * ex;
    }

    const float inv = (den > 0.f) ? (1.f / den) : 0.f;
    sm[off] = s * inv;
    __syncthreads();

    if (w == 0) {
        float m = 0.f;
        #pragma unroll
        for (int h = 0; h < 6; h++) m += sm[h * 32 + lane];
        out[(size_t)node * 32 + lane] = m * (1.f / 6.f) + resm[(size_t)node * 64 + lane];
    }
}

// ===========================================================================
// Host driver
// ===========================================================================
extern "C" void kernel_launch(void* const* d_in, const int* in_sizes, int n_in,
                              void* d_out, int out_size)
{
    const float* x   = (const float*)d_in[0];
    const int*   src = (const int*)d_in[1];
    const int*   dst = (const int*)d_in[2];
    const float* W0s = (const float*)d_in[3];
    const float* b0s = (const float*)d_in[4];
    const float* W0d = (const float*)d_in[5];
    const float* b0d = (const float*)d_in[6];
    const float* a0  = (const float*)d_in[7];
    const float* W1s = (const float*)d_in[8];
    const float* b1s = (const float*)d_in[9];
    const float* W1d = (const float*)d_in[10];
    const float* b1d = (const float*)d_in[11];
    const float* a1  = (const float*)d_in[12];
    const float* W2s = (const float*)d_in[13];
    const float* b2s = (const float*)d_in[14];
    const float* W2d = (const float*)d_in[15];
    const float* b2d = (const float*)d_in[16];
    const float* a2  = (const float*)d_in[17];
    const float* Wr2 = (const float*)d_in[18];
    const float* br2 = (const float*)d_in[19];

    const int N = in_sizes[0] / 128;
    const int E = in_sizes[1];

    float *FS, *FD, *HA, *BR2M;
    __nv_bfloat16 *AH, *AL, *WH, *WL;
    int *CNT, *ROWPTR, *CURS, *COL, *BLKSUM;
    cudaGetSymbolAddress((void**)&FS, g_FS);
    cudaGetSymbolAddress((void**)&FD, g_FD);
    cudaGetSymbolAddress((void**)&HA, g_HA);
    cudaGetSymbolAddress((void**)&BR2M, g_BR2M);
    cudaGetSymbolAddress((void**)&AH, g_AH);
    cudaGetSymbolAddress((void**)&AL, g_AL);
    cudaGetSymbolAddress((void**)&WH, g_WH);
    cudaGetSymbolAddress((void**)&WL, g_WL);
    cudaGetSymbolAddress((void**)&CNT, g_CNT);
    cudaGetSymbolAddress((void**)&ROWPTR, g_ROWPTR);
    cudaGetSymbolAddress((void**)&CURS, g_CURS);
    cudaGetSymbolAddress((void**)&COL, g_COL);
    cudaGetSymbolAddress((void**)&BLKSUM, g_BLKSUM);

    float* out = (float*)d_out;

    const int TB = 256;
    const int mTiles = cdiv(N, 128);

    // order: wconv(1) conv_x(2) hist(3) scan_blk(4) gemm0(5) scan_fix(6) fill(7)...
    {
        WcP wp;
        wp.W[0] = W0s; wp.W[1] = W0d; wp.W[2] = W1s; wp.W[3] = W1d;
        wp.W[4] = W2s; wp.W[5] = W2d; wp.Wr2 = Wr2; wp.br2 = br2;
        wconv_kernel<<<cdiv(WT_TOTAL, TB), TB>>>(wp, WH, WL, BR2M);
    }
    conv_x_kernel<<<cdiv(N * 128, TB), TB>>>(x, AH, AL, N * 128);
    hist_kernel<<<cdiv(E, TB), TB>>>(dst, CNT, E);
    scan_blk_kernel<<<SCAN_G, SCAN_B>>>(CNT, ROWPTR, BLKSUM, N);

    // ---------------- Layer 0 GEMM: K=128 -> FS, FD ----------------
    {
        MmaP P;
        for (int i = 0; i < 8; i++) { P.selMap[i] = i >> 2; P.colMap[i] = (i & 3) * 64; }
        P.woff[0] = 0;     P.bias[0] = b0s; P.C[0] = FS; P.Cld[0] = 256;
        P.woff[1] = 32768; P.bias[1] = b0d; P.C[1] = FD; P.Cld[1] = 256;
        P.woff[2] = 0;     P.bias[2] = b0s; P.C[2] = FS; P.Cld[2] = 256;
        dim3 grid(mTiles, 8);
        gemm_mma_kernel<<<grid, 256>>>(AH, AL, WH, WL, P, N, 128);
    }

    scan_fix_kernel<<<SCAN_G, SCAN_B>>>(BLKSUM, ROWPTR, CURS, N);
    fill_kernel<<<cdiv(E, TB), TB>>>(src, dst, CURS, COL, E);

    gat_agg_h4d64_kernel<0, 1><<<N, 128>>>(ROWPTR, COL, FS, FD, a0, nullptr, HA, AH, AL);

    // ---------------- Layer 1: K=256 -> FS, FD ----------------
    {
        MmaP P;
        for (int i = 0; i < 8; i++) { P.selMap[i] = i >> 2; P.colMap[i] = (i & 3) * 64; }
        P.woff[0] = 65536;  P.bias[0] = b1s; P.C[0] = FS; P.Cld[0] = 256;
        P.woff[1] = 131072; P.bias[1] = b1d; P.C[1] = FD; P.Cld[1] = 256;
        P.woff[2] = 0;      P.bias[2] = b1s; P.C[2] = FS; P.Cld[2] = 256;
        dim3 grid(mTiles, 8);
        gemm_mma_kernel<<<grid, 256>>>(AH, AL, WH, WL, P, N, 256);
    }
    gat_agg_h4d64_kernel<1, 0><<<N, 128>>>(ROWPTR, COL, FS, FD, a1, HA, nullptr, AH, AL);

    // ---------------- Layer 2: K=256 -> FS, FD (192) + resm (64) ------
    {
        MmaP P;
        const int sm_[7] = {0, 0, 0, 1, 1, 1, 2};
        const int cm_[7] = {0, 64, 128, 0, 64, 128, 0};
        for (int i = 0; i < 7; i++) { P.selMap[i] = sm_[i]; P.colMap[i] = cm_[i]; }
        P.selMap[7] = 0; P.colMap[7] = 0;
        P.woff[0] = 196608; P.bias[0] = b2s;  P.C[0] = FS; P.Cld[0] = 192;
        P.woff[1] = 245760; P.bias[1] = b2d;  P.C[1] = FD; P.Cld[1] = 192;
        P.woff[2] = 294912; P.bias[2] = BR2M; P.C[2] = HA; P.Cld[2] = 64;
        dim3 grid(mTiles, 7);
        gemm_mma_kernel<<<grid, 256>>>(AH, AL, WH, WL, P, N, 256);
    }
    gat_agg_l2_kernel<<<N, 192>>>(ROWPTR, COL, FS, FD, a2, HA, out);
}